// round 1
// baseline (speedup 1.0000x reference)
#include <cuda_runtime.h>
#include <math.h>

#define B_TOT 16384
#define EDIM  128
#define HIST  50
#define KC    1920   // compact c width (zero fields removed)
#define H1    512
#define H2    256

// scratch (allocation-free rule: __device__ globals)
__device__ float g_c [(size_t)B_TOT * KC];
__device__ float g_h1[(size_t)B_TOT * H1];
__device__ float g_h2[(size_t)B_TOT * H2];

#define SPB 8   // samples per block in feature kernel

// ---------------------------------------------------------------------------
// K1: gathers + mm-proj(Linear+LN+ReLU) + hist pooling + SENet + bilinear
// writes compact c: [xs f1..f5 (640) | pairs (i,j) i>=1 (1280)]
// ---------------------------------------------------------------------------
__global__ __launch_bounds__(128) void feat_kernel(
    const int*   __restrict__ item_id,
    const float* __restrict__ in128,
    const int*   __restrict__ likes,
    const int*   __restrict__ views,
    const int*   __restrict__ seq,
    const float* __restrict__ item_emb,
    const float* __restrict__ cate_emb,
    const float* __restrict__ mm_W,
    const float* __restrict__ mm_b,
    const float* __restrict__ ln_g,
    const float* __restrict__ ln_b,
    const float* __restrict__ se_W1,
    const float* __restrict__ se_b1,
    const float* __restrict__ se_W2,
    const float* __restrict__ se_b2,
    const float* __restrict__ bi_W)
{
    __shared__ float sh_in[SPB][EDIM];
    __shared__ float sh_xs[SPB][6][EDIM];
    __shared__ int   sh_seq[SPB][HIST];
    __shared__ int   sh_id[SPB], sh_lk[SPB], sh_vw[SPB];
    __shared__ float sh_mu[SPB], sh_rs[SPB];
    __shared__ float sh_w[SPB][6];

    const int e  = threadIdx.x;
    const int b0 = blockIdx.x * SPB;

    if (e < SPB) {
        sh_id[e] = item_id[b0 + e];
        sh_lk[e] = likes[b0 + e];
        sh_vw[e] = views[b0 + e];
    }
    for (int i = e; i < SPB * HIST; i += 128)
        sh_seq[i / HIST][i % HIST] = seq[(size_t)(b0 + i / HIST) * HIST + (i % HIST)];
    for (int s = 0; s < SPB; s++)
        sh_in[s][e] = in128[(size_t)(b0 + s) * EDIM + e];
    __syncthreads();

    // mm matvec: mm[s][e] = mm_b[e] + sum_k in[s][k] * mm_W[k][e]
    float acc[SPB];
    {
        float bv = mm_b[e];
        #pragma unroll
        for (int s = 0; s < SPB; s++) acc[s] = bv;
        for (int k = 0; k < EDIM; k++) {
            float w = mm_W[k * EDIM + e];
            #pragma unroll
            for (int s = 0; s < SPB; s++) acc[s] += sh_in[s][k] * w;
        }
    }

    // fields (pre-SE x): 0=user(zero) 1=like 2=view 3=item 4=mm(pre-LN) 5=hist
    for (int s = 0; s < SPB; s++) {
        sh_xs[s][0][e] = 0.f;
        sh_xs[s][1][e] = cate_emb[sh_lk[s] * EDIM + e];
        sh_xs[s][2][e] = cate_emb[sh_vw[s] * EDIM + e];
        int id = sh_id[s];
        sh_xs[s][3][e] = id ? item_emb[(size_t)id * EDIM + e] : 0.f;
        sh_xs[s][4][e] = acc[s];
        float h = 0.f; int cnt = 0;
        #pragma unroll 5
        for (int t = 0; t < HIST; t++) {
            int sid = sh_seq[s][t];
            if (sid) { h += item_emb[(size_t)sid * EDIM + e]; cnt++; }
        }
        sh_xs[s][5][e] = h / (float)max(cnt, 1);
    }
    __syncthreads();

    const int warp = e >> 5, lane = e & 31;

    // LayerNorm stats for field 4
    for (int s = warp; s < SPB; s += 4) {
        float sum = 0.f, sq = 0.f;
        #pragma unroll
        for (int i = 0; i < 4; i++) {
            float v = sh_xs[s][4][lane + 32 * i];
            sum += v; sq += v * v;
        }
        #pragma unroll
        for (int o = 16; o > 0; o >>= 1) {
            sum += __shfl_xor_sync(0xffffffffu, sum, o);
            sq  += __shfl_xor_sync(0xffffffffu, sq,  o);
        }
        if (lane == 0) {
            float mu = sum * (1.f / 128.f);
            float var = sq * (1.f / 128.f) - mu * mu;
            sh_mu[s] = mu;
            sh_rs[s] = rsqrtf(var + 1e-5f);
        }
    }
    __syncthreads();
    {
        float g = ln_g[e], bb = ln_b[e];
        for (int s = 0; s < SPB; s++) {
            float v = (sh_xs[s][4][e] - sh_mu[s]) * sh_rs[s] * g + bb;
            sh_xs[s][4][e] = fmaxf(v, 0.f);
        }
    }
    __syncthreads();

    // SENet: z[f]=mean_e x; w = sigmoid(relu(z@W1+b1)@W2+b2)
    for (int s = warp; s < SPB; s += 4) {
        float z[6];
        #pragma unroll
        for (int f = 0; f < 6; f++) {
            float sum = 0.f;
            #pragma unroll
            for (int i = 0; i < 4; i++) sum += sh_xs[s][f][lane + 32 * i];
            #pragma unroll
            for (int o = 16; o > 0; o >>= 1) sum += __shfl_xor_sync(0xffffffffu, sum, o);
            z[f] = sum * (1.f / 128.f);
        }
        if (lane == 0) {
            float h[3];
            #pragma unroll
            for (int j = 0; j < 3; j++) {
                float a = se_b1[j];
                #pragma unroll
                for (int f = 0; f < 6; f++) a += z[f] * se_W1[f * 3 + j];
                h[j] = fmaxf(a, 0.f);
            }
            #pragma unroll
            for (int f = 0; f < 6; f++) {
                float a = se_b2[f];
                #pragma unroll
                for (int j = 0; j < 3; j++) a += h[j] * se_W2[j * 6 + f];
                sh_w[s][f] = 1.f / (1.f + expf(-a));
            }
        }
    }
    __syncthreads();

    // scale: xs = x * w ; write xs fields 1..5 to compact c cols [0,640)
    for (int s = 0; s < SPB; s++) {
        #pragma unroll
        for (int f = 0; f < 6; f++) {
            float v = sh_xs[s][f][e] * sh_w[s][f];
            sh_xs[s][f][e] = v;
            if (f >= 1) g_c[(size_t)(b0 + s) * KC + (f - 1) * EDIM + e] = v;
        }
    }
    __syncthreads();

    // bilinear: xw[j] = xs[j] @ bi_W for j=2..5; pairs (i,j) i>=1
    #pragma unroll
    for (int j = 2; j < 6; j++) {
        float xw[SPB];
        #pragma unroll
        for (int s = 0; s < SPB; s++) xw[s] = 0.f;
        for (int k = 0; k < EDIM; k++) {
            float w = bi_W[k * EDIM + e];
            #pragma unroll
            for (int s = 0; s < SPB; s++) xw[s] += sh_xs[s][j][k] * w;
        }
        #pragma unroll
        for (int i = 1; i < j; i++) {
            // pair index among (i<j, i>=1) in lex order
            int idx = (i - 1) * 5 - (i - 1) * i / 2 + (j - i - 1);
            #pragma unroll
            for (int s = 0; s < SPB; s++) {
                g_c[(size_t)(b0 + s) * KC + 640 + idx * EDIM + e] =
                    sh_xs[s][i][e] * xw[s];
            }
        }
    }
}

// ---------------------------------------------------------------------------
// Tiled fp32 GEMM + bias + BatchNorm(eval) + ReLU epilogue.
// C[M,N] = relu(bn(A[M,K] @ Bw[K',N] + bias)), K' rows remapped if MAP_K.
// BM=BN=128, BK=16, 256 threads, 8x8 micro-tiles.
// ---------------------------------------------------------------------------
template <bool MAP_K>
__global__ __launch_bounds__(256) void gemm_bn_relu(
    const float* __restrict__ A, int lda,
    const float* __restrict__ Bw, int ldb,
    const float* __restrict__ bias,
    const float* __restrict__ bn_g, const float* __restrict__ bn_b,
    const float* __restrict__ bn_rm, const float* __restrict__ bn_rv,
    float* __restrict__ C, int ldc,
    int M, int N, int K)
{
    __shared__ __align__(16) float sA[16][128];
    __shared__ __align__(16) float sB[16][128];

    const int tid = threadIdx.x;
    const int tx = tid & 15, ty = tid >> 4;
    const int row0 = blockIdx.y * 128;
    const int col0 = blockIdx.x * 128;

    float acc[8][8];
    #pragma unroll
    for (int i = 0; i < 8; i++)
        #pragma unroll
        for (int j = 0; j < 8; j++) acc[i][j] = 0.f;

    for (int kt = 0; kt < K; kt += 16) {
        // load A tile 128x16 -> transposed sA[k][m]
        #pragma unroll
        for (int i = 0; i < 2; i++) {
            int r = (tid >> 2) + i * 64;
            int c = (tid & 3) * 4;
            float4 v = *(const float4*)(A + (size_t)(row0 + r) * lda + kt + c);
            sA[c + 0][r] = v.x; sA[c + 1][r] = v.y;
            sA[c + 2][r] = v.z; sA[c + 3][r] = v.w;
        }
        // load B tile 16x128
        #pragma unroll
        for (int i = 0; i < 2; i++) {
            int r = (tid >> 5) + i * 8;
            int c = (tid & 31) * 4;
            int src = kt + r;
            if (MAP_K) src = (src < 640) ? (src + 128) : (src + 768);
            *(float4*)&sB[r][c] = *(const float4*)(Bw + (size_t)src * ldb + col0 + c);
        }
        __syncthreads();
        #pragma unroll
        for (int k = 0; k < 16; k++) {
            float4 a0 = *(const float4*)&sA[k][ty * 8];
            float4 a1 = *(const float4*)&sA[k][ty * 8 + 4];
            float4 b0 = *(const float4*)&sB[k][tx * 8];
            float4 b1 = *(const float4*)&sB[k][tx * 8 + 4];
            float av[8] = {a0.x, a0.y, a0.z, a0.w, a1.x, a1.y, a1.z, a1.w};
            float bv[8] = {b0.x, b0.y, b0.z, b0.w, b1.x, b1.y, b1.z, b1.w};
            #pragma unroll
            for (int i = 0; i < 8; i++)
                #pragma unroll
                for (int j = 0; j < 8; j++) acc[i][j] += av[i] * bv[j];
        }
        __syncthreads();
    }

    #pragma unroll
    for (int j = 0; j < 8; j++) {
        int n = col0 + tx * 8 + j;
        float bi = bias[n];
        float sc = bn_g[n] * rsqrtf(bn_rv[n] + 1e-5f);
        float sh = bn_b[n] - bn_rm[n] * sc;
        #pragma unroll
        for (int i = 0; i < 8; i++) {
            int m = row0 + ty * 8 + i;
            float v = (acc[i][j] + bi) * sc + sh;
            C[(size_t)m * ldc + n] = fmaxf(v, 0.f);
        }
    }
}

// ---------------------------------------------------------------------------
// K4: final 256 -> 1 dot + sigmoid, warp per sample
// ---------------------------------------------------------------------------
__global__ __launch_bounds__(256) void head_kernel(
    const float* __restrict__ W3, const float* __restrict__ b3,
    float* __restrict__ out)
{
    const int warp = threadIdx.x >> 5, lane = threadIdx.x & 31;
    const int s = blockIdx.x * 8 + warp;
    const float* h = g_h2 + (size_t)s * H2;
    float sum = 0.f;
    #pragma unroll
    for (int i = 0; i < 8; i++) {
        int c = lane + 32 * i;
        sum += h[c] * W3[c];
    }
    #pragma unroll
    for (int o = 16; o > 0; o >>= 1) sum += __shfl_xor_sync(0xffffffffu, sum, o);
    if (lane == 0) out[s] = 1.f / (1.f + expf(-(sum + b3[0])));
}

// ---------------------------------------------------------------------------
extern "C" void kernel_launch(void* const* d_in, const int* in_sizes, int n_in,
                              void* d_out, int out_size)
{
    const int*   item_id  = (const int*)  d_in[0];
    const float* in128    = (const float*)d_in[1];
    const int*   likes    = (const int*)  d_in[2];
    const int*   views    = (const int*)  d_in[3];
    const int*   seq      = (const int*)  d_in[4];
    const float* item_emb = (const float*)d_in[5];
    const float* cate_emb = (const float*)d_in[6];
    const float* mm_W     = (const float*)d_in[7];
    const float* mm_b     = (const float*)d_in[8];
    const float* ln_g     = (const float*)d_in[9];
    const float* ln_b     = (const float*)d_in[10];
    const float* se_W1    = (const float*)d_in[11];
    const float* se_b1    = (const float*)d_in[12];
    const float* se_W2    = (const float*)d_in[13];
    const float* se_b2    = (const float*)d_in[14];
    const float* bi_W     = (const float*)d_in[15];
    const float* mlp_W1   = (const float*)d_in[16];
    const float* mlp_b1   = (const float*)d_in[17];
    const float* bn1_g    = (const float*)d_in[18];
    const float* bn1_b    = (const float*)d_in[19];
    const float* bn1_rm   = (const float*)d_in[20];
    const float* bn1_rv   = (const float*)d_in[21];
    const float* mlp_W2   = (const float*)d_in[22];
    const float* mlp_b2   = (const float*)d_in[23];
    const float* bn2_g    = (const float*)d_in[24];
    const float* bn2_b    = (const float*)d_in[25];
    const float* bn2_rm   = (const float*)d_in[26];
    const float* bn2_rv   = (const float*)d_in[27];
    const float* mlp_W3   = (const float*)d_in[28];
    const float* mlp_b3   = (const float*)d_in[29];
    float* out = (float*)d_out;

    float *c_ptr, *h1_ptr, *h2_ptr;
    cudaGetSymbolAddress((void**)&c_ptr,  g_c);
    cudaGetSymbolAddress((void**)&h1_ptr, g_h1);
    cudaGetSymbolAddress((void**)&h2_ptr, g_h2);

    feat_kernel<<<B_TOT / SPB, 128>>>(
        item_id, in128, likes, views, seq, item_emb, cate_emb,
        mm_W, mm_b, ln_g, ln_b, se_W1, se_b1, se_W2, se_b2, bi_W);

    gemm_bn_relu<true><<<dim3(H1 / 128, B_TOT / 128), 256>>>(
        c_ptr, KC, mlp_W1, H1, mlp_b1,
        bn1_g, bn1_b, bn1_rm, bn1_rv,
        h1_ptr, H1, B_TOT, H1, KC);

    gemm_bn_relu<false><<<dim3(H2 / 128, B_TOT / 128), 256>>>(
        h1_ptr, H1, mlp_W2, H2, mlp_b2,
        bn2_g, bn2_b, bn2_rm, bn2_rv,
        h2_ptr, H2, B_TOT, H2, H1);

    head_kernel<<<B_TOT / 8, 256>>>(mlp_W3, mlp_b3, out);
}

// round 4
// speedup vs baseline: 1.9888x; 1.9888x over previous
#include <cuda_runtime.h>
#include <cuda.h>
#include <cuda_bf16.h>
#include <cstdint>
#include <math.h>

#define B_TOT 16384
#define EDIM  128
#define HIST  50
#define KC    1920   // compact c width (zero fields removed)
#define H1    512
#define H2    256

// ---------------- scratch (__device__ globals; no allocations) -------------
__device__ __align__(1024) __nv_bfloat16 g_c_hi [(size_t)B_TOT * KC];
__device__ __align__(1024) __nv_bfloat16 g_c_lo [(size_t)B_TOT * KC];
__device__ __align__(1024) __nv_bfloat16 g_W1t_hi[(size_t)H1 * KC];
__device__ __align__(1024) __nv_bfloat16 g_W1t_lo[(size_t)H1 * KC];
__device__ __align__(1024) __nv_bfloat16 g_h1_hi[(size_t)B_TOT * H1];
__device__ __align__(1024) __nv_bfloat16 g_h1_lo[(size_t)B_TOT * H1];
__device__ __align__(1024) __nv_bfloat16 g_W2t_hi[(size_t)H2 * H1];
__device__ __align__(1024) __nv_bfloat16 g_W2t_lo[(size_t)H2 * H1];
__device__ __align__(1024) float         g_h2   [(size_t)B_TOT * H2];

// ---------------------------- PTX helpers ----------------------------------
__device__ __forceinline__ uint32_t smem_u32(const void* p) {
    uint32_t a;
    asm("{ .reg .u64 t; cvta.to.shared.u64 t, %1; cvt.u32.u64 %0, t; }"
        : "=r"(a) : "l"(p));
    return a;
}
__device__ __forceinline__ void mbar_init(uint32_t addr, uint32_t cnt) {
    asm volatile("mbarrier.init.shared.b64 [%0], %1;" :: "r"(addr), "r"(cnt) : "memory");
}
__device__ __forceinline__ void mbar_expect_tx(uint32_t addr, uint32_t bytes) {
    asm volatile("mbarrier.arrive.expect_tx.shared.b64 _, [%0], %1;"
        :: "r"(addr), "r"(bytes) : "memory");
}
__device__ __forceinline__ void mbar_wait(uint32_t addr, uint32_t phase) {
    asm volatile(
        "{\n\t.reg .pred P;\n\t"
        "WL_%=:\n\t"
        "mbarrier.try_wait.parity.acquire.cta.shared::cta.b64 P, [%0], %1, 0x989680;\n\t"
        "@P bra.uni WD_%=;\n\t"
        "bra.uni WL_%=;\n\t"
        "WD_%=:\n\t}"
        :: "r"(addr), "r"(phase) : "memory");
}
__device__ __forceinline__ void tma2d(uint32_t dst, const CUtensorMap* m,
                                      int x, int y, uint32_t bar) {
    asm volatile(
        "cp.async.bulk.tensor.2d.shared::cta.global.tile.mbarrier::complete_tx::bytes "
        "[%0], [%1, {%2, %3}], [%4];"
        :: "r"(dst), "l"(m), "r"(x), "r"(y), "r"(bar) : "memory");
}
__device__ __forceinline__ void ldm_x4(uint32_t* r, uint32_t a) {
    asm volatile("ldmatrix.sync.aligned.m8n8.x4.shared.b16 {%0,%1,%2,%3}, [%4];"
        : "=r"(r[0]), "=r"(r[1]), "=r"(r[2]), "=r"(r[3]) : "r"(a));
}
__device__ __forceinline__ void mma16816(float* c, const uint32_t* a,
                                         uint32_t b0, uint32_t b1) {
    asm volatile(
        "mma.sync.aligned.m16n8k16.row.col.f32.bf16.bf16.f32 "
        "{%0,%1,%2,%3}, {%4,%5,%6,%7}, {%8,%9}, {%0,%1,%2,%3};"
        : "+f"(c[0]), "+f"(c[1]), "+f"(c[2]), "+f"(c[3])
        : "r"(a[0]), "r"(a[1]), "r"(a[2]), "r"(a[3]), "r"(b0), "r"(b1));
}

// ---------------------------------------------------------------------------
// K1: gathers + mm-proj(Linear+LN+ReLU) + hist pooling + SENet + bilinear
// writes compact c (split hi/lo bf16): [xs f1..f5 (640) | pairs i>=1 (1280)]
// ---------------------------------------------------------------------------
#define SPB 8
__global__ __launch_bounds__(128) void feat_kernel(
    const int*   __restrict__ item_id,
    const float* __restrict__ in128,
    const int*   __restrict__ likes,
    const int*   __restrict__ views,
    const int*   __restrict__ seq,
    const float* __restrict__ item_emb,
    const float* __restrict__ cate_emb,
    const float* __restrict__ mm_W,
    const float* __restrict__ mm_b,
    const float* __restrict__ ln_g,
    const float* __restrict__ ln_b,
    const float* __restrict__ se_W1,
    const float* __restrict__ se_b1,
    const float* __restrict__ se_W2,
    const float* __restrict__ se_b2,
    const float* __restrict__ bi_W)
{
    __shared__ float sh_in[SPB][EDIM];
    __shared__ float sh_xs[SPB][6][EDIM];
    __shared__ int   sh_seq[SPB][HIST];
    __shared__ int   sh_id[SPB], sh_lk[SPB], sh_vw[SPB];
    __shared__ float sh_mu[SPB], sh_rs[SPB];
    __shared__ float sh_w[SPB][6];

    const int e  = threadIdx.x;
    const int b0 = blockIdx.x * SPB;

    if (e < SPB) {
        sh_id[e] = item_id[b0 + e];
        sh_lk[e] = likes[b0 + e];
        sh_vw[e] = views[b0 + e];
    }
    for (int i = e; i < SPB * HIST; i += 128)
        sh_seq[i / HIST][i % HIST] = seq[(size_t)(b0 + i / HIST) * HIST + (i % HIST)];
    for (int s = 0; s < SPB; s++)
        sh_in[s][e] = in128[(size_t)(b0 + s) * EDIM + e];
    __syncthreads();

    float acc[SPB];
    {
        float bv = mm_b[e];
        #pragma unroll
        for (int s = 0; s < SPB; s++) acc[s] = bv;
        for (int k = 0; k < EDIM; k++) {
            float w = mm_W[k * EDIM + e];
            #pragma unroll
            for (int s = 0; s < SPB; s++) acc[s] += sh_in[s][k] * w;
        }
    }

    for (int s = 0; s < SPB; s++) {
        sh_xs[s][0][e] = 0.f;
        sh_xs[s][1][e] = cate_emb[sh_lk[s] * EDIM + e];
        sh_xs[s][2][e] = cate_emb[sh_vw[s] * EDIM + e];
        int id = sh_id[s];
        sh_xs[s][3][e] = id ? item_emb[(size_t)id * EDIM + e] : 0.f;
        sh_xs[s][4][e] = acc[s];
        float h = 0.f; int cnt = 0;
        #pragma unroll 5
        for (int t = 0; t < HIST; t++) {
            int sid = sh_seq[s][t];
            if (sid) { h += item_emb[(size_t)sid * EDIM + e]; cnt++; }
        }
        sh_xs[s][5][e] = h / (float)max(cnt, 1);
    }
    __syncthreads();

    const int warp = e >> 5, lane = e & 31;

    for (int s = warp; s < SPB; s += 4) {
        float sum = 0.f, sq = 0.f;
        #pragma unroll
        for (int i = 0; i < 4; i++) {
            float v = sh_xs[s][4][lane + 32 * i];
            sum += v; sq += v * v;
        }
        #pragma unroll
        for (int o = 16; o > 0; o >>= 1) {
            sum += __shfl_xor_sync(0xffffffffu, sum, o);
            sq  += __shfl_xor_sync(0xffffffffu, sq,  o);
        }
        if (lane == 0) {
            float mu = sum * (1.f / 128.f);
            float var = sq * (1.f / 128.f) - mu * mu;
            sh_mu[s] = mu;
            sh_rs[s] = rsqrtf(var + 1e-5f);
        }
    }
    __syncthreads();
    {
        float g = ln_g[e], bb = ln_b[e];
        for (int s = 0; s < SPB; s++) {
            float v = (sh_xs[s][4][e] - sh_mu[s]) * sh_rs[s] * g + bb;
            sh_xs[s][4][e] = fmaxf(v, 0.f);
        }
    }
    __syncthreads();

    for (int s = warp; s < SPB; s += 4) {
        float z[6];
        #pragma unroll
        for (int f = 0; f < 6; f++) {
            float sum = 0.f;
            #pragma unroll
            for (int i = 0; i < 4; i++) sum += sh_xs[s][f][lane + 32 * i];
            #pragma unroll
            for (int o = 16; o > 0; o >>= 1) sum += __shfl_xor_sync(0xffffffffu, sum, o);
            z[f] = sum * (1.f / 128.f);
        }
        if (lane == 0) {
            float h[3];
            #pragma unroll
            for (int j = 0; j < 3; j++) {
                float a = se_b1[j];
                #pragma unroll
                for (int f = 0; f < 6; f++) a += z[f] * se_W1[f * 3 + j];
                h[j] = fmaxf(a, 0.f);
            }
            #pragma unroll
            for (int f = 0; f < 6; f++) {
                float a = se_b2[f];
                #pragma unroll
                for (int j = 0; j < 3; j++) a += h[j] * se_W2[j * 6 + f];
                sh_w[s][f] = 1.f / (1.f + expf(-a));
            }
        }
    }
    __syncthreads();

    for (int s = 0; s < SPB; s++) {
        #pragma unroll
        for (int f = 0; f < 6; f++) {
            float v = sh_xs[s][f][e] * sh_w[s][f];
            sh_xs[s][f][e] = v;
            if (f >= 1) {
                size_t idx = (size_t)(b0 + s) * KC + (f - 1) * EDIM + e;
                __nv_bfloat16 h = __float2bfloat16(v);
                g_c_hi[idx] = h;
                g_c_lo[idx] = __float2bfloat16(v - __bfloat162float(h));
            }
        }
    }
    __syncthreads();

    #pragma unroll
    for (int j = 2; j < 6; j++) {
        float xw[SPB];
        #pragma unroll
        for (int s = 0; s < SPB; s++) xw[s] = 0.f;
        for (int k = 0; k < EDIM; k++) {
            float w = bi_W[k * EDIM + e];
            #pragma unroll
            for (int s = 0; s < SPB; s++) xw[s] += sh_xs[s][j][k] * w;
        }
        #pragma unroll
        for (int i = 1; i < j; i++) {
            int idx = (i - 1) * 5 - (i - 1) * i / 2 + (j - i - 1);
            #pragma unroll
            for (int s = 0; s < SPB; s++) {
                float v = sh_xs[s][i][e] * xw[s];
                size_t o = (size_t)(b0 + s) * KC + 640 + idx * EDIM + e;
                __nv_bfloat16 h = __float2bfloat16(v);
                g_c_hi[o] = h;
                g_c_lo[o] = __float2bfloat16(v - __bfloat162float(h));
            }
        }
    }
}

// ---------------------------------------------------------------------------
// prep: transpose + hi/lo split of W1 (with compact-K remap) and W2
// ---------------------------------------------------------------------------
__global__ __launch_bounds__(256) void prep_w(const float* __restrict__ W1,
                                              const float* __restrict__ W2)
{
    int i = blockIdx.x * blockDim.x + threadIdx.x;
    const int T1 = H1 * KC;
    const int T2 = H2 * H1;
    if (i < T1) {
        int n = i / KC, k = i - n * KC;
        int src = (k < 640) ? (k + 128) : (k + 768);
        float v = W1[(size_t)src * H1 + n];
        __nv_bfloat16 h = __float2bfloat16(v);
        g_W1t_hi[i] = h;
        g_W1t_lo[i] = __float2bfloat16(v - __bfloat162float(h));
    } else if (i < T1 + T2) {
        int j = i - T1;
        int n = j / H1, k = j - n * H1;
        float v = W2[(size_t)k * H2 + n];
        __nv_bfloat16 h = __float2bfloat16(v);
        g_W2t_hi[j] = h;
        g_W2t_lo[j] = __float2bfloat16(v - __bfloat162float(h));
    }
}

// ---------------------------------------------------------------------------
// mma.sync split-bf16 GEMM (3 passes) with TMA double-buffered loads.
// CTA tile M=128, N=128, K-step 64. 8 warps (2x4), warp tile 64x32.
// Stage smem: Ah|Al|Bh|Bl, 16KB each, SW128-swizzled by TMA.
// ---------------------------------------------------------------------------
#define GM_STAGE 65536
#define GM_EPI   (2 * GM_STAGE)        // 131072 : 2*128 floats
#define GM_MBAR  (GM_EPI + 1024)       // 132096 : 2 mbarriers
#define GM_SMEM  (GM_MBAR + 16)        // 132112

template <bool SPLIT_OUT>
__global__ __launch_bounds__(256, 1) void mma_gemm(
    const __grid_constant__ CUtensorMap mAh,
    const __grid_constant__ CUtensorMap mAl,
    const __grid_constant__ CUtensorMap mBh,
    const __grid_constant__ CUtensorMap mBl,
    int K, int n_tiles,
    const float* __restrict__ bias, const float* __restrict__ bn_g,
    const float* __restrict__ bn_b, const float* __restrict__ bn_rm,
    const float* __restrict__ bn_rv,
    __nv_bfloat16* __restrict__ o_hi, __nv_bfloat16* __restrict__ o_lo,
    float* __restrict__ o_f, int ldo)
{
    extern __shared__ __align__(1024) char smem[];
    const uint32_t sbase = smem_u32(smem);
    const int tid = threadIdx.x, wid = tid >> 5, lane = tid & 31;
    const int mt = blockIdx.x / n_tiles, nt = blockIdx.x - mt * n_tiles;
    const int m0 = mt * 128, n0 = nt * 128;
    const int warp_m = (wid >> 2) * 64, warp_n = (wid & 3) * 32;
    float* epi = (float*)(smem + GM_EPI);
    const uint32_t mb = sbase + GM_MBAR;

    if (tid == 0) { mbar_init(mb, 1); mbar_init(mb + 8, 1); }
    if (tid < 128) {
        int n = n0 + tid;
        float sc = bn_g[n] * rsqrtf(bn_rv[n] + 1e-5f);
        epi[tid] = sc;
        epi[128 + tid] = bn_b[n] - bn_rm[n] * sc + bias[n] * sc;
    }
    __syncthreads();

    const int S = K / 64;
    auto issue = [&](int s) {
        uint32_t bo = sbase + (s & 1) * GM_STAGE;
        uint32_t bar = mb + (s & 1) * 8;
        int kt = s * 64;
        mbar_expect_tx(bar, 65536u);
        tma2d(bo,         &mAh, kt, m0, bar);
        tma2d(bo + 16384, &mAl, kt, m0, bar);
        tma2d(bo + 32768, &mBh, kt, n0, bar);
        tma2d(bo + 49152, &mBl, kt, n0, bar);
    };
    if (tid == 0) { issue(0); issue(1); }

    float acc[4][4][4] = {};

    for (int s = 0; s < S; s++) {
        mbar_wait(mb + (s & 1) * 8, (s >> 1) & 1);
        const uint32_t so = sbase + (s & 1) * GM_STAGE;
        #pragma unroll
        for (int kk = 0; kk < 4; kk++) {
            uint32_t ah[4][4], al[4][4];
            #pragma unroll
            for (int mi = 0; mi < 4; mi++) {
                int r = warp_m + mi * 16 + (lane & 15);
                int j = kk * 2 + (lane >> 4);
                uint32_t o = r * 128 + j * 16;
                o ^= (o >> 3) & 0x70;
                ldm_x4(ah[mi], so + o);
                ldm_x4(al[mi], so + 16384 + o);
            }
            uint32_t bh[2][4], bl[2][4];
            #pragma unroll
            for (int nb = 0; nb < 2; nb++) {
                int r = warp_n + nb * 16 + (lane & 15);
                int j = kk * 2 + (lane >> 4);
                uint32_t o = r * 128 + j * 16;
                o ^= (o >> 3) & 0x70;
                ldm_x4(bh[nb], so + 32768 + o);
                ldm_x4(bl[nb], so + 49152 + o);
            }
            #pragma unroll
            for (int mi = 0; mi < 4; mi++)
                #pragma unroll
                for (int ni = 0; ni < 4; ni++) {
                    int nb = ni >> 1, sl = ni & 1;
                    mma16816(acc[mi][ni], ah[mi], bh[nb][sl], bh[nb][sl + 2]);
                    mma16816(acc[mi][ni], ah[mi], bl[nb][sl], bl[nb][sl + 2]);
                    mma16816(acc[mi][ni], al[mi], bh[nb][sl], bh[nb][sl + 2]);
                }
        }
        __syncthreads();
        if (tid == 0 && s + 2 < S) issue(s + 2);
    }

    // epilogue
    const int gid = lane >> 2, tig = lane & 3;
    #pragma unroll
    for (int mi = 0; mi < 4; mi++) {
        #pragma unroll
        for (int ni = 0; ni < 4; ni++) {
            int ce = warp_n + ni * 8 + tig * 2;
            int col = n0 + ce;
            float sc0 = epi[ce],     sh0 = epi[128 + ce];
            float sc1 = epi[ce + 1], sh1 = epi[128 + ce + 1];
            #pragma unroll
            for (int h = 0; h < 2; h++) {
                int r = m0 + warp_m + mi * 16 + gid + h * 8;
                float v0 = fmaxf(acc[mi][ni][h * 2 + 0] * sc0 + sh0, 0.f);
                float v1 = fmaxf(acc[mi][ni][h * 2 + 1] * sc1 + sh1, 0.f);
                if (SPLIT_OUT) {
                    __nv_bfloat16 h0 = __float2bfloat16(v0);
                    __nv_bfloat16 h1 = __float2bfloat16(v1);
                    __nv_bfloat162 hv; hv.x = h0; hv.y = h1;
                    __nv_bfloat162 lv;
                    lv.x = __float2bfloat16(v0 - __bfloat162float(h0));
                    lv.y = __float2bfloat16(v1 - __bfloat162float(h1));
                    *(__nv_bfloat162*)(o_hi + (size_t)r * ldo + col) = hv;
                    *(__nv_bfloat162*)(o_lo + (size_t)r * ldo + col) = lv;
                } else {
                    float2 fv; fv.x = v0; fv.y = v1;
                    *(float2*)(o_f + (size_t)r * ldo + col) = fv;
                }
            }
        }
    }
}

// ---------------------------------------------------------------------------
// K4: final 256 -> 1 dot + sigmoid, warp per sample
// ---------------------------------------------------------------------------
__global__ __launch_bounds__(256) void head_kernel(
    const float* __restrict__ W3, const float* __restrict__ b3,
    float* __restrict__ out)
{
    const int warp = threadIdx.x >> 5, lane = threadIdx.x & 31;
    const int s = blockIdx.x * 8 + warp;
    const float* h = g_h2 + (size_t)s * H2;
    float sum = 0.f;
    #pragma unroll
    for (int i = 0; i < 8; i++) {
        int c = lane + 32 * i;
        sum += h[c] * W3[c];
    }
    #pragma unroll
    for (int o = 16; o > 0; o >>= 1) sum += __shfl_xor_sync(0xffffffffu, sum, o);
    if (lane == 0) out[s] = 1.f / (1.f + expf(-(sum + b3[0])));
}

// ---------------------------------------------------------------------------
typedef CUresult (*PFN_encode_t)(
    CUtensorMap*, CUtensorMapDataType, cuuint32_t, void*,
    const cuuint64_t*, const cuuint64_t*, const cuuint32_t*, const cuuint32_t*,
    CUtensorMapInterleave, CUtensorMapSwizzle, CUtensorMapL2promotion,
    CUtensorMapFloatOOBfill);

static void build_map(PFN_encode_t enc, CUtensorMap* m, void* base,
                      uint64_t k_elems, uint64_t rows) {
    cuuint64_t dims[2]    = {k_elems, rows};
    cuuint64_t strides[1] = {k_elems * 2};
    cuuint32_t box[2]     = {64, 128};
    cuuint32_t es[2]      = {1, 1};
    enc(m, CU_TENSOR_MAP_DATA_TYPE_BFLOAT16, 2, base, dims, strides, box, es,
        CU_TENSOR_MAP_INTERLEAVE_NONE, CU_TENSOR_MAP_SWIZZLE_128B,
        CU_TENSOR_MAP_L2_PROMOTION_L2_128B, CU_TENSOR_MAP_FLOAT_OOB_FILL_NONE);
}

extern "C" void kernel_launch(void* const* d_in, const int* in_sizes, int n_in,
                              void* d_out, int out_size)
{
    const int*   item_id  = (const int*)  d_in[0];
    const float* in128    = (const float*)d_in[1];
    const int*   likes    = (const int*)  d_in[2];
    const int*   views    = (const int*)  d_in[3];
    const int*   seq      = (const int*)  d_in[4];
    const float* item_emb = (const float*)d_in[5];
    const float* cate_emb = (const float*)d_in[6];
    const float* mm_W     = (const float*)d_in[7];
    const float* mm_b     = (const float*)d_in[8];
    const float* ln_g     = (const float*)d_in[9];
    const float* ln_b     = (const float*)d_in[10];
    const float* se_W1    = (const float*)d_in[11];
    const float* se_b1    = (const float*)d_in[12];
    const float* se_W2    = (const float*)d_in[13];
    const float* se_b2    = (const float*)d_in[14];
    const float* bi_W     = (const float*)d_in[15];
    const float* mlp_W1   = (const float*)d_in[16];
    const float* mlp_b1   = (const float*)d_in[17];
    const float* bn1_g    = (const float*)d_in[18];
    const float* bn1_b    = (const float*)d_in[19];
    const float* bn1_rm   = (const float*)d_in[20];
    const float* bn1_rv   = (const float*)d_in[21];
    const float* mlp_W2   = (const float*)d_in[22];
    const float* mlp_b2   = (const float*)d_in[23];
    const float* bn2_g    = (const float*)d_in[24];
    const float* bn2_b    = (const float*)d_in[25];
    const float* bn2_rm   = (const float*)d_in[26];
    const float* bn2_rv   = (const float*)d_in[27];
    const float* mlp_W3   = (const float*)d_in[28];
    const float* mlp_b3   = (const float*)d_in[29];
    float* out = (float*)d_out;

    void *c_hi, *c_lo, *w1_hi, *w1_lo, *h1_hi, *h1_lo, *w2_hi, *w2_lo, *h2;
    cudaGetSymbolAddress(&c_hi,  g_c_hi);
    cudaGetSymbolAddress(&c_lo,  g_c_lo);
    cudaGetSymbolAddress(&w1_hi, g_W1t_hi);
    cudaGetSymbolAddress(&w1_lo, g_W1t_lo);
    cudaGetSymbolAddress(&h1_hi, g_h1_hi);
    cudaGetSymbolAddress(&h1_lo, g_h1_lo);
    cudaGetSymbolAddress(&w2_hi, g_W2t_hi);
    cudaGetSymbolAddress(&w2_lo, g_W2t_lo);
    cudaGetSymbolAddress(&h2,    g_h2);

    // driver entry point for tensormap encoding (no -lcuda needed)
    void* fn = nullptr;
    cudaDriverEntryPointQueryResult qr;
    cudaGetDriverEntryPointByVersion("cuTensorMapEncodeTiled", &fn, 12000,
                                     cudaEnableDefault, &qr);
    PFN_encode_t enc = (PFN_encode_t)fn;

    CUtensorMap mAh1, mAl1, mBh1, mBl1, mAh2, mAl2, mBh2, mBl2;
    build_map(enc, &mAh1, c_hi,  KC, B_TOT);
    build_map(enc, &mAl1, c_lo,  KC, B_TOT);
    build_map(enc, &mBh1, w1_hi, KC, H1);
    build_map(enc, &mBl1, w1_lo, KC, H1);
    build_map(enc, &mAh2, h1_hi, H1, B_TOT);
    build_map(enc, &mAl2, h1_lo, H1, B_TOT);
    build_map(enc, &mBh2, w2_hi, H1, H2);
    build_map(enc, &mBl2, w2_lo, H1, H2);

    cudaFuncSetAttribute(mma_gemm<true>,
                         cudaFuncAttributeMaxDynamicSharedMemorySize, GM_SMEM);
    cudaFuncSetAttribute(mma_gemm<false>,
                         cudaFuncAttributeMaxDynamicSharedMemorySize, GM_SMEM);

    feat_kernel<<<B_TOT / SPB, 128>>>(
        item_id, in128, likes, views, seq, item_emb, cate_emb,
        mm_W, mm_b, ln_g, ln_b, se_W1, se_b1, se_W2, se_b2, bi_W);

    prep_w<<<(H1 * KC + H2 * H1 + 255) / 256, 256>>>(mlp_W1, mlp_W2);

    // MLP1: M=16384, N=512 (4 n-tiles), K=1920
    mma_gemm<true><<<(B_TOT / 128) * 4, 256, GM_SMEM>>>(
        mAh1, mAl1, mBh1, mBl1, KC, 4,
        mlp_b1, bn1_g, bn1_b, bn1_rm, bn1_rv,
        (__nv_bfloat16*)h1_hi, (__nv_bfloat16*)h1_lo, nullptr, H1);

    // MLP2: M=16384, N=256 (2 n-tiles), K=512
    mma_gemm<false><<<(B_TOT / 128) * 2, 256, GM_SMEM>>>(
        mAh2, mAl2, mBh2, mBl2, H1, 2,
        mlp_b2, bn2_g, bn2_b, bn2_rm, bn2_rv,
        nullptr, nullptr, (float*)h2, H2);

    head_kernel<<<B_TOT / 8, 256>>>(mlp_W3, mlp_b3, out);
}

// round 7
// speedup vs baseline: 2.2492x; 1.1309x over previous
#include <cuda_runtime.h>
#include <cuda.h>
#include <cuda_bf16.h>
#include <cstdint>
#include <math.h>

#define B_TOT 16384
#define EDIM  128
#define HIST  50
#define KC    1920   // compact c width (zero fields removed)
#define H1    512
#define H2    256

// ---------------- scratch (__device__ globals; no allocations) -------------
__device__ __align__(1024) __nv_bfloat16 g_c_hi [(size_t)B_TOT * KC];
__device__ __align__(1024) __nv_bfloat16 g_c_lo [(size_t)B_TOT * KC];
__device__ __align__(1024) __nv_bfloat16 g_W1t_hi[(size_t)H1 * KC];
__device__ __align__(1024) __nv_bfloat16 g_W1t_lo[(size_t)H1 * KC];
__device__ __align__(1024) __nv_bfloat16 g_h1_hi[(size_t)B_TOT * H1];
__device__ __align__(1024) __nv_bfloat16 g_h1_lo[(size_t)B_TOT * H1];
__device__ __align__(1024) __nv_bfloat16 g_W2t_hi[(size_t)H2 * H1];
__device__ __align__(1024) __nv_bfloat16 g_W2t_lo[(size_t)H2 * H1];
__device__ __align__(1024) float         g_h2   [(size_t)B_TOT * H2];

// ---------------------------- PTX helpers ----------------------------------
__device__ __forceinline__ uint32_t smem_u32(const void* p) {
    uint32_t a;
    asm("{ .reg .u64 t; cvta.to.shared.u64 t, %1; cvt.u32.u64 %0, t; }"
        : "=r"(a) : "l"(p));
    return a;
}
__device__ __forceinline__ void mbar_init(uint32_t addr, uint32_t cnt) {
    asm volatile("mbarrier.init.shared.b64 [%0], %1;" :: "r"(addr), "r"(cnt) : "memory");
}
__device__ __forceinline__ void mbar_expect_tx(uint32_t addr, uint32_t bytes) {
    asm volatile("mbarrier.arrive.expect_tx.shared.b64 _, [%0], %1;"
        :: "r"(addr), "r"(bytes) : "memory");
}
__device__ __forceinline__ void mbar_wait(uint32_t addr, uint32_t phase) {
    asm volatile(
        "{\n\t.reg .pred P;\n\t"
        "WL_%=:\n\t"
        "mbarrier.try_wait.parity.acquire.cta.shared::cta.b64 P, [%0], %1, 0x989680;\n\t"
        "@P bra.uni WD_%=;\n\t"
        "bra.uni WL_%=;\n\t"
        "WD_%=:\n\t}"
        :: "r"(addr), "r"(phase) : "memory");
}
__device__ __forceinline__ void tma2d(uint32_t dst, const CUtensorMap* m,
                                      int x, int y, uint32_t bar) {
    asm volatile(
        "cp.async.bulk.tensor.2d.shared::cta.global.tile.mbarrier::complete_tx::bytes "
        "[%0], [%1, {%2, %3}], [%4];"
        :: "r"(dst), "l"(m), "r"(x), "r"(y), "r"(bar) : "memory");
}
__device__ __forceinline__ void ldm_x4(uint32_t* r, uint32_t a) {
    asm volatile("ldmatrix.sync.aligned.m8n8.x4.shared.b16 {%0,%1,%2,%3}, [%4];"
        : "=r"(r[0]), "=r"(r[1]), "=r"(r[2]), "=r"(r[3]) : "r"(a));
}
__device__ __forceinline__ void mma16816(float* c, const uint32_t* a,
                                         uint32_t b0, uint32_t b1) {
    asm volatile(
        "mma.sync.aligned.m16n8k16.row.col.f32.bf16.bf16.f32 "
        "{%0,%1,%2,%3}, {%4,%5,%6,%7}, {%8,%9}, {%0,%1,%2,%3};"
        : "+f"(c[0]), "+f"(c[1]), "+f"(c[2]), "+f"(c[3])
        : "r"(a[0]), "r"(a[1]), "r"(a[2]), "r"(a[3]), "r"(b0), "r"(b1));
}

// ---------------------------------------------------------------------------
// K1: gathers + mm-proj(Linear+LN+ReLU) + hist pooling + SENet + bilinear
// writes compact c (split hi/lo bf16): [xs f1..f5 (640) | pairs i>=1 (1280)]
// SPB=4: 4096 blocks of 128 threads — shorter serial chains, better hiding.
// ---------------------------------------------------------------------------
#define SPB 4
__global__ __launch_bounds__(128) void feat_kernel(
    const int*   __restrict__ item_id,
    const float* __restrict__ in128,
    const int*   __restrict__ likes,
    const int*   __restrict__ views,
    const int*   __restrict__ seq,
    const float* __restrict__ item_emb,
    const float* __restrict__ cate_emb,
    const float* __restrict__ mm_W,
    const float* __restrict__ mm_b,
    const float* __restrict__ ln_g,
    const float* __restrict__ ln_b,
    const float* __restrict__ se_W1,
    const float* __restrict__ se_b1,
    const float* __restrict__ se_W2,
    const float* __restrict__ se_b2,
    const float* __restrict__ bi_W)
{
    __shared__ float sh_in[SPB][EDIM];
    __shared__ float sh_xs[SPB][6][EDIM];
    __shared__ int   sh_seq[SPB][HIST];
    __shared__ int   sh_id[SPB], sh_lk[SPB], sh_vw[SPB];
    __shared__ float sh_mu[SPB], sh_rs[SPB];
    __shared__ float sh_w[SPB][6];

    const int e  = threadIdx.x;
    const int b0 = blockIdx.x * SPB;

    if (e < SPB) {
        sh_id[e] = item_id[b0 + e];
        sh_lk[e] = likes[b0 + e];
        sh_vw[e] = views[b0 + e];
    }
    for (int i = e; i < SPB * HIST; i += 128)
        sh_seq[i / HIST][i % HIST] = seq[(size_t)(b0 + i / HIST) * HIST + (i % HIST)];
    #pragma unroll
    for (int s = 0; s < SPB; s++)
        sh_in[s][e] = in128[(size_t)(b0 + s) * EDIM + e];
    __syncthreads();

    float acc[SPB];
    {
        float bv = mm_b[e];
        #pragma unroll
        for (int s = 0; s < SPB; s++) acc[s] = bv;
        for (int k = 0; k < EDIM; k++) {
            float w = mm_W[k * EDIM + e];
            #pragma unroll
            for (int s = 0; s < SPB; s++) acc[s] += sh_in[s][k] * w;
        }
    }

    #pragma unroll
    for (int s = 0; s < SPB; s++) {
        sh_xs[s][0][e] = 0.f;
        sh_xs[s][1][e] = cate_emb[sh_lk[s] * EDIM + e];
        sh_xs[s][2][e] = cate_emb[sh_vw[s] * EDIM + e];
        int id = sh_id[s];
        sh_xs[s][3][e] = id ? item_emb[(size_t)id * EDIM + e] : 0.f;
        sh_xs[s][4][e] = acc[s];
        float h = 0.f; int cnt = 0;
        #pragma unroll 5
        for (int t = 0; t < HIST; t++) {
            int sid = sh_seq[s][t];
            if (sid) { h += item_emb[(size_t)sid * EDIM + e]; cnt++; }
        }
        sh_xs[s][5][e] = h / (float)max(cnt, 1);
    }
    __syncthreads();

    const int warp = e >> 5, lane = e & 31;

    // LN stats: warp s handles sample s
    {
        const int s = warp;
        float sum = 0.f, sq = 0.f;
        #pragma unroll
        for (int i = 0; i < 4; i++) {
            float v = sh_xs[s][4][lane + 32 * i];
            sum += v; sq += v * v;
        }
        #pragma unroll
        for (int o = 16; o > 0; o >>= 1) {
            sum += __shfl_xor_sync(0xffffffffu, sum, o);
            sq  += __shfl_xor_sync(0xffffffffu, sq,  o);
        }
        if (lane == 0) {
            float mu = sum * (1.f / 128.f);
            float var = sq * (1.f / 128.f) - mu * mu;
            sh_mu[s] = mu;
            sh_rs[s] = rsqrtf(var + 1e-5f);
        }
    }
    __syncthreads();
    {
        float g = ln_g[e], bb = ln_b[e];
        #pragma unroll
        for (int s = 0; s < SPB; s++) {
            float v = (sh_xs[s][4][e] - sh_mu[s]) * sh_rs[s] * g + bb;
            sh_xs[s][4][e] = fmaxf(v, 0.f);
        }
    }
    __syncthreads();

    // SENet: warp s handles sample s
    {
        const int s = warp;
        float z[6];
        #pragma unroll
        for (int f = 0; f < 6; f++) {
            float sum = 0.f;
            #pragma unroll
            for (int i = 0; i < 4; i++) sum += sh_xs[s][f][lane + 32 * i];
            #pragma unroll
            for (int o = 16; o > 0; o >>= 1) sum += __shfl_xor_sync(0xffffffffu, sum, o);
            z[f] = sum * (1.f / 128.f);
        }
        if (lane == 0) {
            float h[3];
            #pragma unroll
            for (int j = 0; j < 3; j++) {
                float a = se_b1[j];
                #pragma unroll
                for (int f = 0; f < 6; f++) a += z[f] * se_W1[f * 3 + j];
                h[j] = fmaxf(a, 0.f);
            }
            #pragma unroll
            for (int f = 0; f < 6; f++) {
                float a = se_b2[f];
                #pragma unroll
                for (int j = 0; j < 3; j++) a += h[j] * se_W2[j * 6 + f];
                sh_w[s][f] = 1.f / (1.f + expf(-a));
            }
        }
    }
    __syncthreads();

    #pragma unroll
    for (int s = 0; s < SPB; s++) {
        #pragma unroll
        for (int f = 0; f < 6; f++) {
            float v = sh_xs[s][f][e] * sh_w[s][f];
            sh_xs[s][f][e] = v;
            if (f >= 1) {
                size_t idx = (size_t)(b0 + s) * KC + (f - 1) * EDIM + e;
                __nv_bfloat16 h = __float2bfloat16(v);
                g_c_hi[idx] = h;
                g_c_lo[idx] = __float2bfloat16(v - __bfloat162float(h));
            }
        }
    }
    __syncthreads();

    #pragma unroll
    for (int j = 2; j < 6; j++) {
        float xw[SPB];
        #pragma unroll
        for (int s = 0; s < SPB; s++) xw[s] = 0.f;
        for (int k = 0; k < EDIM; k++) {
            float w = bi_W[k * EDIM + e];
            #pragma unroll
            for (int s = 0; s < SPB; s++) xw[s] += sh_xs[s][j][k] * w;
        }
        #pragma unroll
        for (int i = 1; i < j; i++) {
            int idx = (i - 1) * 5 - (i - 1) * i / 2 + (j - i - 1);
            #pragma unroll
            for (int s = 0; s < SPB; s++) {
                float v = sh_xs[s][i][e] * xw[s];
                size_t o = (size_t)(b0 + s) * KC + 640 + idx * EDIM + e;
                __nv_bfloat16 h = __float2bfloat16(v);
                g_c_hi[o] = h;
                g_c_lo[o] = __float2bfloat16(v - __bfloat162float(h));
            }
        }
    }
}

// ---------------------------------------------------------------------------
// prep: transpose + hi/lo split of W1 (with compact-K remap) and W2
// ---------------------------------------------------------------------------
__global__ __launch_bounds__(256) void prep_w(const float* __restrict__ W1,
                                              const float* __restrict__ W2)
{
    int i = blockIdx.x * blockDim.x + threadIdx.x;
    const int T1 = H1 * KC;
    const int T2 = H2 * H1;
    if (i < T1) {
        int n = i / KC, k = i - n * KC;
        int src = (k < 640) ? (k + 128) : (k + 768);
        float v = W1[(size_t)src * H1 + n];
        __nv_bfloat16 h = __float2bfloat16(v);
        g_W1t_hi[i] = h;
        g_W1t_lo[i] = __float2bfloat16(v - __bfloat162float(h));
    } else if (i < T1 + T2) {
        int j = i - T1;
        int n = j / H1, k = j - n * H1;
        float v = W2[(size_t)k * H2 + n];
        __nv_bfloat16 h = __float2bfloat16(v);
        g_W2t_hi[j] = h;
        g_W2t_lo[j] = __float2bfloat16(v - __bfloat162float(h));
    }
}

// ---------------------------------------------------------------------------
// mma.sync split-bf16 GEMM (3 passes) with TMA 3-stage pipelined loads.
// CTA tile M=128, N=128, K-step 64. 8 warps (2x4), warp tile 64x32.
// Pass-major MMA ordering: 16 independent accumulators between acc reuse.
// ---------------------------------------------------------------------------
#define GM_STAGE 65536
#define GM_NSTG  3
#define GM_EPI   (GM_NSTG * GM_STAGE)       // 196608
#define GM_MBAR  (GM_EPI + 1024)            // 197632
#define GM_SMEM  (GM_MBAR + 32)             // 197664

template <bool SPLIT_OUT>
__global__ __launch_bounds__(256, 1) void mma_gemm(
    const __grid_constant__ CUtensorMap mAh,
    const __grid_constant__ CUtensorMap mAl,
    const __grid_constant__ CUtensorMap mBh,
    const __grid_constant__ CUtensorMap mBl,
    int K, int n_tiles,
    const float* __restrict__ bias, const float* __restrict__ bn_g,
    const float* __restrict__ bn_b, const float* __restrict__ bn_rm,
    const float* __restrict__ bn_rv,
    __nv_bfloat16* __restrict__ o_hi, __nv_bfloat16* __restrict__ o_lo,
    float* __restrict__ o_f, int ldo)
{
    extern __shared__ __align__(1024) char smem[];
    const uint32_t sbase = smem_u32(smem);
    const int tid = threadIdx.x, wid = tid >> 5, lane = tid & 31;
    const int mt = blockIdx.x / n_tiles, nt = blockIdx.x - mt * n_tiles;
    const int m0 = mt * 128, n0 = nt * 128;
    const int warp_m = (wid >> 2) * 64, warp_n = (wid & 3) * 32;
    float* epi = (float*)(smem + GM_EPI);
    const uint32_t mb = sbase + GM_MBAR;

    if (tid == 0) {
        mbar_init(mb, 1); mbar_init(mb + 8, 1); mbar_init(mb + 16, 1);
    }
    if (tid < 128) {
        int n = n0 + tid;
        float sc = bn_g[n] * rsqrtf(bn_rv[n] + 1e-5f);
        epi[tid] = sc;
        epi[128 + tid] = bn_b[n] - bn_rm[n] * sc + bias[n] * sc;
    }
    __syncthreads();

    const int S = K / 64;
    auto issue = [&](int s) {
        int b = s % GM_NSTG;
        uint32_t bo = sbase + b * GM_STAGE;
        uint32_t bar = mb + b * 8;
        int kt = s * 64;
        mbar_expect_tx(bar, 65536u);
        tma2d(bo,         &mAh, kt, m0, bar);
        tma2d(bo + 16384, &mAl, kt, m0, bar);
        tma2d(bo + 32768, &mBh, kt, n0, bar);
        tma2d(bo + 49152, &mBl, kt, n0, bar);
    };
    if (tid == 0) { issue(0); issue(1); issue(2); }

    float acc[4][4][4] = {};

    for (int s = 0; s < S; s++) {
        const int b = s % GM_NSTG;
        mbar_wait(mb + b * 8, (s / GM_NSTG) & 1);
        const uint32_t so = sbase + b * GM_STAGE;
        #pragma unroll
        for (int kk = 0; kk < 4; kk++) {
            uint32_t ah[4][4], al[4][4];
            #pragma unroll
            for (int mi = 0; mi < 4; mi++) {
                int r = warp_m + mi * 16 + (lane & 15);
                int j = kk * 2 + (lane >> 4);
                uint32_t o = r * 128 + j * 16;
                o ^= (o >> 3) & 0x70;
                ldm_x4(ah[mi], so + o);
                ldm_x4(al[mi], so + 16384 + o);
            }
            uint32_t bh[2][4], bl[2][4];
            #pragma unroll
            for (int nb = 0; nb < 2; nb++) {
                int r = warp_n + nb * 16 + (lane & 15);
                int j = kk * 2 + (lane >> 4);
                uint32_t o = r * 128 + j * 16;
                o ^= (o >> 3) & 0x70;
                ldm_x4(bh[nb], so + 32768 + o);
                ldm_x4(bl[nb], so + 49152 + o);
            }
            // pass-major: 16 independent accumulators between reuse of any acc
            #pragma unroll
            for (int mi = 0; mi < 4; mi++)
                #pragma unroll
                for (int ni = 0; ni < 4; ni++)
                    mma16816(acc[mi][ni], ah[mi], bh[ni >> 1][ni & 1], bh[ni >> 1][(ni & 1) + 2]);
            #pragma unroll
            for (int mi = 0; mi < 4; mi++)
                #pragma unroll
                for (int ni = 0; ni < 4; ni++)
                    mma16816(acc[mi][ni], ah[mi], bl[ni >> 1][ni & 1], bl[ni >> 1][(ni & 1) + 2]);
            #pragma unroll
            for (int mi = 0; mi < 4; mi++)
                #pragma unroll
                for (int ni = 0; ni < 4; ni++)
                    mma16816(acc[mi][ni], al[mi], bh[ni >> 1][ni & 1], bh[ni >> 1][(ni & 1) + 2]);
        }
        __syncthreads();
        if (tid == 0 && s + GM_NSTG < S) issue(s + GM_NSTG);
    }

    // epilogue
    const int gid = lane >> 2, tig = lane & 3;
    #pragma unroll
    for (int mi = 0; mi < 4; mi++) {
        #pragma unroll
        for (int ni = 0; ni < 4; ni++) {
            int ce = warp_n + ni * 8 + tig * 2;
            int col = n0 + ce;
            float sc0 = epi[ce],     sh0 = epi[128 + ce];
            float sc1 = epi[ce + 1], sh1 = epi[128 + ce + 1];
            #pragma unroll
            for (int h = 0; h < 2; h++) {
                int r = m0 + warp_m + mi * 16 + gid + h * 8;
                float v0 = fmaxf(acc[mi][ni][h * 2 + 0] * sc0 + sh0, 0.f);
                float v1 = fmaxf(acc[mi][ni][h * 2 + 1] * sc1 + sh1, 0.f);
                if (SPLIT_OUT) {
                    __nv_bfloat16 h0 = __float2bfloat16(v0);
                    __nv_bfloat16 h1 = __float2bfloat16(v1);
                    __nv_bfloat162 hv; hv.x = h0; hv.y = h1;
                    __nv_bfloat162 lv;
                    lv.x = __float2bfloat16(v0 - __bfloat162float(h0));
                    lv.y = __float2bfloat16(v1 - __bfloat162float(h1));
                    *(__nv_bfloat162*)(o_hi + (size_t)r * ldo + col) = hv;
                    *(__nv_bfloat162*)(o_lo + (size_t)r * ldo + col) = lv;
                } else {
                    float2 fv; fv.x = v0; fv.y = v1;
                    *(float2*)(o_f + (size_t)r * ldo + col) = fv;
                }
            }
        }
    }
}

// ---------------------------------------------------------------------------
// K4: final 256 -> 1 dot + sigmoid, warp per sample
// ---------------------------------------------------------------------------
__global__ __launch_bounds__(256) void head_kernel(
    const float* __restrict__ W3, const float* __restrict__ b3,
    float* __restrict__ out)
{
    const int warp = threadIdx.x >> 5, lane = threadIdx.x & 31;
    const int s = blockIdx.x * 8 + warp;
    const float* h = g_h2 + (size_t)s * H2;
    float sum = 0.f;
    #pragma unroll
    for (int i = 0; i < 8; i++) {
        int c = lane + 32 * i;
        sum += h[c] * W3[c];
    }
    #pragma unroll
    for (int o = 16; o > 0; o >>= 1) sum += __shfl_xor_sync(0xffffffffu, sum, o);
    if (lane == 0) out[s] = 1.f / (1.f + expf(-(sum + b3[0])));
}

// ---------------------------------------------------------------------------
typedef CUresult (*PFN_encode_t)(
    CUtensorMap*, CUtensorMapDataType, cuuint32_t, void*,
    const cuuint64_t*, const cuuint64_t*, const cuuint32_t*, const cuuint32_t*,
    CUtensorMapInterleave, CUtensorMapSwizzle, CUtensorMapL2promotion,
    CUtensorMapFloatOOBfill);

static void build_map(PFN_encode_t enc, CUtensorMap* m, void* base,
                      uint64_t k_elems, uint64_t rows) {
    cuuint64_t dims[2]    = {k_elems, rows};
    cuuint64_t strides[1] = {k_elems * 2};
    cuuint32_t box[2]     = {64, 128};
    cuuint32_t es[2]      = {1, 1};
    enc(m, CU_TENSOR_MAP_DATA_TYPE_BFLOAT16, 2, base, dims, strides, box, es,
        CU_TENSOR_MAP_INTERLEAVE_NONE, CU_TENSOR_MAP_SWIZZLE_128B,
        CU_TENSOR_MAP_L2_PROMOTION_L2_128B, CU_TENSOR_MAP_FLOAT_OOB_FILL_NONE);
}

extern "C" void kernel_launch(void* const* d_in, const int* in_sizes, int n_in,
                              void* d_out, int out_size)
{
    const int*   item_id  = (const int*)  d_in[0];
    const float* in128    = (const float*)d_in[1];
    const int*   likes    = (const int*)  d_in[2];
    const int*   views    = (const int*)  d_in[3];
    const int*   seq      = (const int*)  d_in[4];
    const float* item_emb = (const float*)d_in[5];
    const float* cate_emb = (const float*)d_in[6];
    const float* mm_W     = (const float*)d_in[7];
    const float* mm_b     = (const float*)d_in[8];
    const float* ln_g     = (const float*)d_in[9];
    const float* ln_b     = (const float*)d_in[10];
    const float* se_W1    = (const float*)d_in[11];
    const float* se_b1    = (const float*)d_in[12];
    const float* se_W2    = (const float*)d_in[13];
    const float* se_b2    = (const float*)d_in[14];
    const float* bi_W     = (const float*)d_in[15];
    const float* mlp_W1   = (const float*)d_in[16];
    const float* mlp_b1   = (const float*)d_in[17];
    const float* bn1_g    = (const float*)d_in[18];
    const float* bn1_b    = (const float*)d_in[19];
    const float* bn1_rm   = (const float*)d_in[20];
    const float* bn1_rv   = (const float*)d_in[21];
    const float* mlp_W2   = (const float*)d_in[22];
    const float* mlp_b2   = (const float*)d_in[23];
    const float* bn2_g    = (const float*)d_in[24];
    const float* bn2_b    = (const float*)d_in[25];
    const float* bn2_rm   = (const float*)d_in[26];
    const float* bn2_rv   = (const float*)d_in[27];
    const float* mlp_W3   = (const float*)d_in[28];
    const float* mlp_b3   = (const float*)d_in[29];
    float* out = (float*)d_out;

    void *c_hi, *c_lo, *w1_hi, *w1_lo, *h1_hi, *h1_lo, *w2_hi, *w2_lo, *h2;
    cudaGetSymbolAddress(&c_hi,  g_c_hi);
    cudaGetSymbolAddress(&c_lo,  g_c_lo);
    cudaGetSymbolAddress(&w1_hi, g_W1t_hi);
    cudaGetSymbolAddress(&w1_lo, g_W1t_lo);
    cudaGetSymbolAddress(&h1_hi, g_h1_hi);
    cudaGetSymbolAddress(&h1_lo, g_h1_lo);
    cudaGetSymbolAddress(&w2_hi, g_W2t_hi);
    cudaGetSymbolAddress(&w2_lo, g_W2t_lo);
    cudaGetSymbolAddress(&h2,    g_h2);

    void* fn = nullptr;
    cudaDriverEntryPointQueryResult qr;
    cudaGetDriverEntryPointByVersion("cuTensorMapEncodeTiled", &fn, 12000,
                                     cudaEnableDefault, &qr);
    PFN_encode_t enc = (PFN_encode_t)fn;

    CUtensorMap mAh1, mAl1, mBh1, mBl1, mAh2, mAl2, mBh2, mBl2;
    build_map(enc, &mAh1, c_hi,  KC, B_TOT);
    build_map(enc, &mAl1, c_lo,  KC, B_TOT);
    build_map(enc, &mBh1, w1_hi, KC, H1);
    build_map(enc, &mBl1, w1_lo, KC, H1);
    build_map(enc, &mAh2, h1_hi, H1, B_TOT);
    build_map(enc, &mAl2, h1_lo, H1, B_TOT);
    build_map(enc, &mBh2, w2_hi, H1, H2);
    build_map(enc, &mBl2, w2_lo, H1, H2);

    cudaFuncSetAttribute(mma_gemm<true>,
                         cudaFuncAttributeMaxDynamicSharedMemorySize, GM_SMEM);
    cudaFuncSetAttribute(mma_gemm<false>,
                         cudaFuncAttributeMaxDynamicSharedMemorySize, GM_SMEM);

    feat_kernel<<<B_TOT / SPB, 128>>>(
        item_id, in128, likes, views, seq, item_emb, cate_emb,
        mm_W, mm_b, ln_g, ln_b, se_W1, se_b1, se_W2, se_b2, bi_W);

    prep_w<<<(H1 * KC + H2 * H1 + 255) / 256, 256>>>(mlp_W1, mlp_W2);

    // MLP1: M=16384, N=512 (4 n-tiles), K=1920
    mma_gemm<true><<<(B_TOT / 128) * 4, 256, GM_SMEM>>>(
        mAh1, mAl1, mBh1, mBl1, KC, 4,
        mlp_b1, bn1_g, bn1_b, bn1_rm, bn1_rv,
        (__nv_bfloat16*)h1_hi, (__nv_bfloat16*)h1_lo, nullptr, H1);

    // MLP2: M=16384, N=256 (2 n-tiles), K=512
    mma_gemm<false><<<(B_TOT / 128) * 2, 256, GM_SMEM>>>(
        mAh2, mAl2, mBh2, mBl2, H1, 2,
        mlp_b2, bn2_g, bn2_b, bn2_rm, bn2_rv,
        nullptr, nullptr, (float*)h2, H2);

    head_kernel<<<B_TOT / 8, 256>>>(mlp_W3, mlp_b3, out);
}